// round 13
// baseline (speedup 1.0000x reference)
#include <cuda_runtime.h>
#include <math.h>

#define T_TOK  8192
#define D_DIM  4096
#define E_EXP  64
#define BM     64
#define BK     32
#define NTHR   256
#define TOPK   8
#define SXROW  132   // floats per xs2 row: 2*BM + 4 pad (16B-aligned rows, bank spread)

// packed fp32 FMA/ADD: per-half IEEE round-to-nearest == two scalar ops, bitwise.
#define FMA2(acc, a, b) asm("fma.rn.f32x2 %0, %1, %2, %0;" : "+l"(acc) : "l"(a), "l"(b))
#define ADD2(acc, b)    asm("add.rn.f32x2 %0, %0, %1;"     : "+l"(acc) : "l"(b))

__device__ __forceinline__ void st_dup(float* p, float v) {
    float2 d = make_float2(v, v);
    *(float2*)p = d;
}

__global__ __launch_bounds__(NTHR, 1)
void router_kernel(const float* __restrict__ x,   // [T, D]
                   const float* __restrict__ w,   // [D, E]
                   float* __restrict__ out,
                   int out_size)
{
    __shared__ float xs2[BK][SXROW];        // k-major, token t duplicated at cols 2t,2t+1
    __shared__ float ws[BK][E_EXP];
    __shared__ float logits[BM][E_EXP + 1];

    const int tid  = threadIdx.x;
    const int tx   = tid & 15;
    const int ty   = tid >> 4;
    const int row0 = blockIdx.x * BM;

    // FROZEN association: 8 contiguous 512-k panels, serial ascending FMA within
    // panel (cha), panels folded ascending into tot. FFMA2 halves are independent
    // IEEE chains (experts 2j, 2j+1) -> bitwise identical to the scalar version.
    unsigned long long tot2[4][2], cha2[4][2];
#pragma unroll
    for (int i = 0; i < 4; ++i)
#pragma unroll
        for (int p = 0; p < 2; ++p) { tot2[i][p] = 0ull; cha2[i][p] = 0ull; }

    const int sx0 = tid, sx1 = tid + 256;
    const int xm0 = sx0 >> 3, xq0 = sx0 & 7;   // token m, k-quad
    const int xm1 = sx1 >> 3, xq1 = sx1 & 7;
    const int wk0 = tid >> 4;
    const int weq = tid & 15;

    const float* xbase = x + (size_t)row0 * D_DIM;

    float4 xr0 = *(const float4*)(xbase + xm0 * D_DIM + xq0 * 4);
    float4 xr1 = *(const float4*)(xbase + xm1 * D_DIM + xq1 * 4);
    float4 wr0 = *(const float4*)(w + (size_t)wk0        * E_EXP + weq * 4);
    float4 wr1 = *(const float4*)(w + (size_t)(wk0 + 16) * E_EXP + weq * 4);

    const int NCHUNK = D_DIM / BK;   // 128 chunks; 16 chunks = one 512-k panel
    for (int c = 0; c < NCHUNK; ++c) {
        // x tile -> k-major duplicated smem
        st_dup(&xs2[xq0 * 4 + 0][2 * xm0], xr0.x);
        st_dup(&xs2[xq0 * 4 + 1][2 * xm0], xr0.y);
        st_dup(&xs2[xq0 * 4 + 2][2 * xm0], xr0.z);
        st_dup(&xs2[xq0 * 4 + 3][2 * xm0], xr0.w);
        st_dup(&xs2[xq1 * 4 + 0][2 * xm1], xr1.x);
        st_dup(&xs2[xq1 * 4 + 1][2 * xm1], xr1.y);
        st_dup(&xs2[xq1 * 4 + 2][2 * xm1], xr1.z);
        st_dup(&xs2[xq1 * 4 + 3][2 * xm1], xr1.w);
        *(float4*)&ws[wk0][weq * 4]      = wr0;
        *(float4*)&ws[wk0 + 16][weq * 4] = wr1;
        __syncthreads();

        if (c + 1 < NCHUNK) {
            const int c0 = (c + 1) * BK;
            xr0 = *(const float4*)(xbase + xm0 * D_DIM + c0 + xq0 * 4);
            xr1 = *(const float4*)(xbase + xm1 * D_DIM + c0 + xq1 * 4);
            wr0 = *(const float4*)(w + (size_t)(c0 + wk0)      * E_EXP + weq * 4);
            wr1 = *(const float4*)(w + (size_t)(c0 + wk0 + 16) * E_EXP + weq * 4);
        }

        // serial ascending k within the panel; 8 FFMA2 per k
#pragma unroll 8
        for (int k = 0; k < BK; ++k) {
            const ulonglong2 xA = *(const ulonglong2*)&xs2[k][8 * ty];      // (t0,t0),(t1,t1)
            const ulonglong2 xB = *(const ulonglong2*)&xs2[k][8 * ty + 4];  // (t2,t2),(t3,t3)
            const ulonglong2 wp = *(const ulonglong2*)&ws[k][tx * 4];       // (w0,w1),(w2,w3)
            FMA2(cha2[0][0], xA.x, wp.x); FMA2(cha2[0][1], xA.x, wp.y);
            FMA2(cha2[1][0], xA.y, wp.x); FMA2(cha2[1][1], xA.y, wp.y);
            FMA2(cha2[2][0], xB.x, wp.x); FMA2(cha2[2][1], xB.x, wp.y);
            FMA2(cha2[3][0], xB.y, wp.x); FMA2(cha2[3][1], xB.y, wp.y);
        }

        // end of a 512-k panel: fold panel sum into total (ascending), reset
        if ((c & 15) == 15) {
#pragma unroll
            for (int i = 0; i < 4; ++i)
#pragma unroll
                for (int p = 0; p < 2; ++p) {
                    ADD2(tot2[i][p], cha2[i][p]);
                    cha2[i][p] = 0ull;
                }
        }
        __syncthreads();
    }

    // unpack packed totals into logits
#pragma unroll
    for (int i = 0; i < 4; ++i)
#pragma unroll
        for (int p = 0; p < 2; ++p) {
            const unsigned long long v = tot2[i][p];
            const unsigned int lo = (unsigned int)v;
            const unsigned int hi = (unsigned int)(v >> 32);
            logits[ty * 4 + i][tx * 4 + 2 * p + 0] = __uint_as_float(lo);
            logits[ty * 4 + i][tx * 4 + 2 * p + 1] = __uint_as_float(hi);
        }
    __syncthreads();

    // ---- top-8 + softmax: one thread per token ----
    if (tid < BM) {
        const float* rowv = &logits[tid][0];
        unsigned long long used = 0ull;
        float vals[TOPK];
        int   idx[TOPK];
#pragma unroll
        for (int s = 0; s < TOPK; ++s) {
            float best = -INFINITY;
            int   bi   = 0;
            for (int e = 0; e < E_EXP; ++e) {
                if (!((used >> e) & 1ull)) {
                    float v = rowv[e];
                    if (v > best) { best = v; bi = e; }
                }
            }
            used |= 1ull << bi;
            vals[s] = best;
            idx[s]  = bi;
        }
        const float mx = vals[0];
        float ev[TOPK];
        float sum = 0.0f;
#pragma unroll
        for (int s = 0; s < TOPK; ++s) { ev[s] = expf(vals[s] - mx); sum += ev[s]; }
        const float inv = 1.0f / sum;

        const int token = row0 + tid;
        float* wout = out + (size_t)token * TOPK;
#pragma unroll
        for (int s = 0; s < TOPK; ++s) wout[s] = ev[s] * inv;

        if (out_size >= T_TOK * TOPK * 2) {
            float* eout = out + (size_t)T_TOK * TOPK + (size_t)token * TOPK;
#pragma unroll
            for (int s = 0; s < TOPK; ++s) eout[s] = (float)idx[s];
        }
    }
}

extern "C" void kernel_launch(void* const* d_in, const int* in_sizes, int n_in,
                              void* d_out, int out_size)
{
    const float* a = (const float*)d_in[0];
    const float* b = (const float*)d_in[1];
    const float* x = a;
    const float* w = b;
    if (n_in >= 2 && in_sizes[0] == D_DIM * E_EXP && in_sizes[1] == T_TOK * D_DIM) {
        x = b; w = a;
    }
    router_kernel<<<T_TOK / BM, NTHR>>>(x, w, (float*)d_out, out_size);
}

// round 14
// speedup vs baseline: 1.2674x; 1.2674x over previous
#include <cuda_runtime.h>
#include <math.h>

#define T_TOK  8192
#define D_DIM  4096
#define E_EXP  64
#define BM     64
#define BK     32
#define NTHR   256
#define TOPK   8
#define XROW   68    // floats per k-major xs row (64 tokens + 4 pad, 16B-aligned)

// packed fp32 FMA/ADD: per-half IEEE round-to-nearest == two scalar ops, bitwise.
#define FMA2(acc, a, b) asm("fma.rn.f32x2 %0, %1, %2, %0;" : "+l"(acc) : "l"(a), "l"(b))
#define ADD2(acc, b)    asm("add.rn.f32x2 %0, %0, %1;"     : "+l"(acc) : "l"(b))
#define PACK2(out, v)   asm("mov.b64 %0, {%1, %1};"        : "=l"(out) : "f"(v))

__global__ __launch_bounds__(NTHR, 1)
void router_kernel(const float* __restrict__ x,   // [T, D]
                   const float* __restrict__ w,   // [D, E]
                   float* __restrict__ out,
                   int out_size)
{
    __shared__ float xs[BK][XROW];          // k-major: xs[k][token]
    __shared__ float ws[BK][E_EXP];
    __shared__ float logits[BM][E_EXP + 1];

    const int tid  = threadIdx.x;
    const int tx   = tid & 15;              // expert quad: experts 4tx..4tx+3
    const int ty   = tid >> 4;              // token quad:  tokens  4ty..4ty+3
    const int row0 = blockIdx.x * BM;

    // FROZEN association: 8 contiguous 512-k panels, serial ascending FMA within
    // panel, panels folded ascending. FFMA2 halves = independent IEEE chains
    // (experts 2j,2j+1) -> bitwise identical to scalar (proven in R13).
    unsigned long long tot2[4][2], cha2[4][2];
#pragma unroll
    for (int i = 0; i < 4; ++i)
#pragma unroll
        for (int p = 0; p < 2; ++p) { tot2[i][p] = 0ull; cha2[i][p] = 0ull; }

    const int sx0 = tid, sx1 = tid + 256;
    const int xm0 = sx0 >> 3, xq0 = sx0 & 7;   // token, k-quad
    const int xm1 = sx1 >> 3, xq1 = sx1 & 7;
    const int wk0 = tid >> 4;
    const int weq = tid & 15;

    const float* xbase = x + (size_t)row0 * D_DIM;

    float4 xr0 = *(const float4*)(xbase + xm0 * D_DIM + xq0 * 4);
    float4 xr1 = *(const float4*)(xbase + xm1 * D_DIM + xq1 * 4);
    float4 wr0 = *(const float4*)(w + (size_t)wk0        * E_EXP + weq * 4);
    float4 wr1 = *(const float4*)(w + (size_t)(wk0 + 16) * E_EXP + weq * 4);

    const int NCHUNK = D_DIM / BK;   // 128 chunks; 16 chunks = one 512-k panel
    for (int c = 0; c < NCHUNK; ++c) {
        // x tile -> k-major smem (scatter by k)
        xs[xq0 * 4 + 0][xm0] = xr0.x;
        xs[xq0 * 4 + 1][xm0] = xr0.y;
        xs[xq0 * 4 + 2][xm0] = xr0.z;
        xs[xq0 * 4 + 3][xm0] = xr0.w;
        xs[xq1 * 4 + 0][xm1] = xr1.x;
        xs[xq1 * 4 + 1][xm1] = xr1.y;
        xs[xq1 * 4 + 2][xm1] = xr1.z;
        xs[xq1 * 4 + 3][xm1] = xr1.w;
        *(float4*)&ws[wk0][weq * 4]      = wr0;
        *(float4*)&ws[wk0 + 16][weq * 4] = wr1;
        __syncthreads();

        if (c + 1 < NCHUNK) {
            const int c0 = (c + 1) * BK;
            xr0 = *(const float4*)(xbase + xm0 * D_DIM + c0 + xq0 * 4);
            xr1 = *(const float4*)(xbase + xm1 * D_DIM + c0 + xq1 * 4);
            wr0 = *(const float4*)(w + (size_t)(c0 + wk0)      * E_EXP + weq * 4);
            wr1 = *(const float4*)(w + (size_t)(c0 + wk0 + 16) * E_EXP + weq * 4);
        }

        // serial ascending k within the panel; 8 FFMA2 + 4 packs per k
#pragma unroll 8
        for (int k = 0; k < BK; ++k) {
            const float4 xt = *(const float4*)&xs[k][ty * 4];              // 4 tokens @ k
            const ulonglong2 wp = *(const ulonglong2*)&ws[k][tx * 4];      // (w0,w1),(w2,w3)
            unsigned long long x0, x1, x2, x3;
            PACK2(x0, xt.x); PACK2(x1, xt.y); PACK2(x2, xt.z); PACK2(x3, xt.w);
            FMA2(cha2[0][0], x0, wp.x); FMA2(cha2[0][1], x0, wp.y);
            FMA2(cha2[1][0], x1, wp.x); FMA2(cha2[1][1], x1, wp.y);
            FMA2(cha2[2][0], x2, wp.x); FMA2(cha2[2][1], x2, wp.y);
            FMA2(cha2[3][0], x3, wp.x); FMA2(cha2[3][1], x3, wp.y);
        }

        // end of a 512-k panel: fold panel sum into total (ascending), reset
        if ((c & 15) == 15) {
#pragma unroll
            for (int i = 0; i < 4; ++i)
#pragma unroll
                for (int p = 0; p < 2; ++p) {
                    ADD2(tot2[i][p], cha2[i][p]);
                    cha2[i][p] = 0ull;
                }
        }
        __syncthreads();
    }

    // unpack packed totals into logits
#pragma unroll
    for (int i = 0; i < 4; ++i)
#pragma unroll
        for (int p = 0; p < 2; ++p) {
            const unsigned long long v = tot2[i][p];
            logits[ty * 4 + i][tx * 4 + 2 * p + 0] = __uint_as_float((unsigned int)v);
            logits[ty * 4 + i][tx * 4 + 2 * p + 1] = __uint_as_float((unsigned int)(v >> 32));
        }
    __syncthreads();

    // ---- top-8 + softmax: one thread per token ----
    if (tid < BM) {
        const float* rowv = &logits[tid][0];
        unsigned long long used = 0ull;
        float vals[TOPK];
        int   idx[TOPK];
#pragma unroll
        for (int s = 0; s < TOPK; ++s) {
            float best = -INFINITY;
            int   bi   = 0;
            for (int e = 0; e < E_EXP; ++e) {
                if (!((used >> e) & 1ull)) {
                    float v = rowv[e];
                    if (v > best) { best = v; bi = e; }
                }
            }
            used |= 1ull << bi;
            vals[s] = best;
            idx[s]  = bi;
        }
        const float mx = vals[0];
        float ev[TOPK];
        float sum = 0.0f;
#pragma unroll
        for (int s = 0; s < TOPK; ++s) { ev[s] = expf(vals[s] - mx); sum += ev[s]; }
        const float inv = 1.0f / sum;

        const int token = row0 + tid;
        float* wout = out + (size_t)token * TOPK;
#pragma unroll
        for (int s = 0; s < TOPK; ++s) wout[s] = ev[s] * inv;

        if (out_size >= T_TOK * TOPK * 2) {
            float* eout = out + (size_t)T_TOK * TOPK + (size_t)token * TOPK;
#pragma unroll
            for (int s = 0; s < TOPK; ++s) eout[s] = (float)idx[s];
        }
    }
}

extern "C" void kernel_launch(void* const* d_in, const int* in_sizes, int n_in,
                              void* d_out, int out_size)
{
    const float* a = (const float*)d_in[0];
    const float* b = (const float*)d_in[1];
    const float* x = a;
    const float* w = b;
    if (n_in >= 2 && in_sizes[0] == D_DIM * E_EXP && in_sizes[1] == T_TOK * D_DIM) {
        x = b; w = a;
    }
    router_kernel<<<T_TOK / BM, NTHR>>>(x, w, (float*)d_out, out_size);
}